// round 2
// baseline (speedup 1.0000x reference)
#include <cuda_runtime.h>
#include <cuda_bf16.h>
#include <cstdint>

// ---------------------------------------------------------------------------
// Problem constants
// ---------------------------------------------------------------------------
#define BATCH 2
#define SEQ   2048
#define EMB   1024
#define HEADS 16
#define HDIM  64
#define MLPH  4096
#define MTOT  (BATCH * SEQ)   // 4096 rows

// ---------------------------------------------------------------------------
// Scratch (device globals: allocation-free)
// ---------------------------------------------------------------------------
__device__ float g_xn [MTOT * EMB];
__device__ float g_q  [MTOT * EMB];
__device__ float g_k  [MTOT * EMB];
__device__ float g_v  [MTOT * EMB];
__device__ float g_att[MTOT * EMB];
__device__ float g_x2 [MTOT * EMB];
__device__ float g_xn2[MTOT * EMB];
__device__ float g_h  [MTOT * MLPH];

// ---------------------------------------------------------------------------
// LayerNorm: one block per row of 1024, 256 threads, float4
// ---------------------------------------------------------------------------
__global__ __launch_bounds__(256) void ln_kernel(
    const float* __restrict__ x, const float* __restrict__ g,
    const float* __restrict__ b, float* __restrict__ y)
{
    int row = blockIdx.x;
    int tid = threadIdx.x;
    const float4 v = ((const float4*)(x + (size_t)row * EMB))[tid];

    float s  = v.x + v.y + v.z + v.w;
    float ss = v.x * v.x + v.y * v.y + v.z * v.z + v.w * v.w;
    #pragma unroll
    for (int o = 16; o; o >>= 1) {
        s  += __shfl_xor_sync(0xffffffffu, s,  o);
        ss += __shfl_xor_sync(0xffffffffu, ss, o);
    }
    __shared__ float rs[8], rss[8];
    int w = tid >> 5, lane = tid & 31;
    if (lane == 0) { rs[w] = s; rss[w] = ss; }
    __syncthreads();
    s = 0.f; ss = 0.f;
    #pragma unroll
    for (int i = 0; i < 8; i++) { s += rs[i]; ss += rss[i]; }

    const float mean = s * (1.0f / EMB);
    const float var  = ss * (1.0f / EMB) - mean * mean;
    const float rstd = rsqrtf(var + 1e-5f);

    const float4 gv = ((const float4*)g)[tid];
    const float4 bv = ((const float4*)b)[tid];
    float4 o;
    o.x = (v.x - mean) * rstd * gv.x + bv.x;
    o.y = (v.y - mean) * rstd * gv.y + bv.y;
    o.z = (v.z - mean) * rstd * gv.z + bv.z;
    o.w = (v.w - mean) * rstd * gv.w + bv.w;
    ((float4*)(y + (size_t)row * EMB))[tid] = o;
}

// ---------------------------------------------------------------------------
// SGEMM: C = A[MxK] @ B[KxN] + bias (+ residual / relu)
// 128x128 tile, BK=16, 256 threads, 8x8 per thread, register prefetch.
// EPI: 0 = bias, 1 = bias+relu, 2 = bias+residual
// Assumes M%128==0, N%128==0, K%16==0.
// ---------------------------------------------------------------------------
template<int EPI>
__global__ __launch_bounds__(256, 1) void sgemm_kernel(
    const float* __restrict__ A, const float* __restrict__ B,
    const float* __restrict__ bias, const float* __restrict__ R,
    float* __restrict__ C, int M, int N, int K)
{
    __shared__ float As[16 * 128];
    __shared__ float Bs[16 * 128];

    const int m0 = blockIdx.y * 128;
    const int n0 = blockIdx.x * 128;
    const int tid = threadIdx.x;
    const int tx = tid & 15;    // 16 col groups
    const int ty = tid >> 4;    // 16 row groups

    // load index precompute: 512 float4 per tile, 2 per thread
    const int i0 = tid, i1 = tid + 256;
    const int ar0 = i0 >> 2, ac0 = (i0 & 3) * 4;
    const int ar1 = i1 >> 2, ac1 = (i1 & 3) * 4;
    const int br0 = i0 >> 5, bc0 = (i0 & 31) * 4;
    const int br1 = i1 >> 5, bc1 = (i1 & 31) * 4;

    const float* Ab = A + (size_t)m0 * K;
    const float* Bb = B + n0;

    float4 pa0 = *(const float4*)(Ab + (size_t)ar0 * K + ac0);
    float4 pa1 = *(const float4*)(Ab + (size_t)ar1 * K + ac1);
    float4 pb0 = *(const float4*)(Bb + (size_t)br0 * N + bc0);
    float4 pb1 = *(const float4*)(Bb + (size_t)br1 * N + bc1);

    float acc[8][8];
    #pragma unroll
    for (int i = 0; i < 8; i++)
        #pragma unroll
        for (int j = 0; j < 8; j++) acc[i][j] = 0.f;

    for (int k0 = 0; k0 < K; k0 += 16) {
        // commit prefetched tile to smem (A transposed to k-major)
        As[(ac0 + 0) * 128 + ar0] = pa0.x;
        As[(ac0 + 1) * 128 + ar0] = pa0.y;
        As[(ac0 + 2) * 128 + ar0] = pa0.z;
        As[(ac0 + 3) * 128 + ar0] = pa0.w;
        As[(ac1 + 0) * 128 + ar1] = pa1.x;
        As[(ac1 + 1) * 128 + ar1] = pa1.y;
        As[(ac1 + 2) * 128 + ar1] = pa1.z;
        As[(ac1 + 3) * 128 + ar1] = pa1.w;
        *(float4*)&Bs[br0 * 128 + bc0] = pb0;
        *(float4*)&Bs[br1 * 128 + bc1] = pb1;
        __syncthreads();

        if (k0 + 16 < K) {  // prefetch next tile (overlaps compute)
            pa0 = *(const float4*)(Ab + (size_t)ar0 * K + (k0 + 16) + ac0);
            pa1 = *(const float4*)(Ab + (size_t)ar1 * K + (k0 + 16) + ac1);
            pb0 = *(const float4*)(Bb + (size_t)(k0 + 16 + br0) * N + bc0);
            pb1 = *(const float4*)(Bb + (size_t)(k0 + 16 + br1) * N + bc1);
        }

        #pragma unroll
        for (int k = 0; k < 16; k++) {
            float a[8], bb[8];
            *(float4*)&a[0]  = *(const float4*)&As[k * 128 + ty * 8];
            *(float4*)&a[4]  = *(const float4*)&As[k * 128 + ty * 8 + 4];
            *(float4*)&bb[0] = *(const float4*)&Bs[k * 128 + tx * 8];
            *(float4*)&bb[4] = *(const float4*)&Bs[k * 128 + tx * 8 + 4];
            #pragma unroll
            for (int i = 0; i < 8; i++)
                #pragma unroll
                for (int j = 0; j < 8; j++)
                    acc[i][j] += a[i] * bb[j];
        }
        __syncthreads();
    }

    // epilogue
    const int gn = n0 + tx * 8;
    float4 bv0 = *(const float4*)(bias + gn);
    float4 bv1 = *(const float4*)(bias + gn + 4);
    #pragma unroll
    for (int i = 0; i < 8; i++) {
        const int gm = m0 + ty * 8 + i;
        float4 o0, o1;
        o0.x = acc[i][0] + bv0.x; o0.y = acc[i][1] + bv0.y;
        o0.z = acc[i][2] + bv0.z; o0.w = acc[i][3] + bv0.w;
        o1.x = acc[i][4] + bv1.x; o1.y = acc[i][5] + bv1.y;
        o1.z = acc[i][6] + bv1.z; o1.w = acc[i][7] + bv1.w;
        if (EPI == 1) {
            o0.x = fmaxf(o0.x, 0.f); o0.y = fmaxf(o0.y, 0.f);
            o0.z = fmaxf(o0.z, 0.f); o0.w = fmaxf(o0.w, 0.f);
            o1.x = fmaxf(o1.x, 0.f); o1.y = fmaxf(o1.y, 0.f);
            o1.z = fmaxf(o1.z, 0.f); o1.w = fmaxf(o1.w, 0.f);
        }
        if (EPI == 2) {
            const float4 r0 = *(const float4*)(R + (size_t)gm * N + gn);
            const float4 r1 = *(const float4*)(R + (size_t)gm * N + gn + 4);
            o0.x += r0.x; o0.y += r0.y; o0.z += r0.z; o0.w += r0.w;
            o1.x += r1.x; o1.y += r1.y; o1.z += r1.z; o1.w += r1.w;
        }
        *(float4*)(C + (size_t)gm * N + gn)     = o0;
        *(float4*)(C + (size_t)gm * N + gn + 4) = o1;
    }
}

// ---------------------------------------------------------------------------
// Flash-attention (fp32, online softmax)
// grid = (SEQ/64, BATCH*HEADS), 256 threads.
// Q/K/V layout: [B, T, H*HDIM] (no transpose; h selects 64-col slice)
// Thread t: query row r = t/4, dh quarter qd = t%4 (16 output cols).
// Key tiles of 32.
// ---------------------------------------------------------------------------
#define QT 64
#define KT 32
#define KST 68   // padded stride for 64-wide rows (float4-aligned)
#define PST 36   // padded stride for 32-wide rows

__global__ __launch_bounds__(256) void attn_kernel(
    const float* __restrict__ Q, const float* __restrict__ Km,
    const float* __restrict__ Vm, float* __restrict__ O)
{
    __shared__ float sQ[QT * KST];
    __shared__ float sK[KT * KST];
    __shared__ float sV[KT * KST];
    __shared__ float sP[QT * PST];

    const int bh = blockIdx.y;
    const int b  = bh / HEADS;
    const int h  = bh % HEADS;
    const int q0 = blockIdx.x * QT;
    const int tid = threadIdx.x;
    const int r  = tid >> 2;   // query row in tile
    const int qd = tid & 3;    // dh quarter

    const size_t base = ((size_t)b * SEQ) * EMB + (size_t)h * HDIM;
    const float* Qb = Q  + base;
    const float* Kb = Km + base;
    const float* Vb = Vm + base;

    // load Q tile, pre-scaled by 1/sqrt(HDIM) = 0.125
    #pragma unroll
    for (int t = 0; t < 4; t++) {
        int idx = tid + t * 256;           // 1024 float4 total
        int qr = idx >> 4, c4 = (idx & 15) * 4;
        float4 v = *(const float4*)(Qb + (size_t)(q0 + qr) * EMB + c4);
        v.x *= 0.125f; v.y *= 0.125f; v.z *= 0.125f; v.w *= 0.125f;
        *(float4*)&sQ[qr * KST + c4] = v;
    }

    float m = -1e30f, l = 0.f;
    float4 acc[4];
    #pragma unroll
    for (int i = 0; i < 4; i++) acc[i] = make_float4(0.f, 0.f, 0.f, 0.f);

    for (int kt = 0; kt < SEQ / KT; kt++) {
        // load K,V tiles: 512 float4 each, 2 per thread per matrix
        #pragma unroll
        for (int t = 0; t < 2; t++) {
            int idx = tid + t * 256;
            int kr = idx >> 4, c4 = (idx & 15) * 4;
            size_t goff = (size_t)(kt * KT + kr) * EMB + c4;
            *(float4*)&sK[kr * KST + c4] = *(const float4*)(Kb + goff);
            *(float4*)&sV[kr * KST + c4] = *(const float4*)(Vb + goff);
        }
        __syncthreads();

        // scores: 8 cols per thread
        float s[8];
        #pragma unroll
        for (int j = 0; j < 8; j++) s[j] = 0.f;
        const float4* q4 = (const float4*)&sQ[r * KST];
        #pragma unroll
        for (int k4 = 0; k4 < 16; k4++) {
            const float4 qv = q4[k4];
            #pragma unroll
            for (int j = 0; j < 8; j++) {
                const float4 kv = *(const float4*)&sK[(qd * 8 + j) * KST + k4 * 4];
                s[j] += qv.x * kv.x + qv.y * kv.y + qv.z * kv.z + qv.w * kv.w;
            }
        }

        // online softmax update (row state shared by 4 threads via shfl)
        float tm = s[0];
        #pragma unroll
        for (int j = 1; j < 8; j++) tm = fmaxf(tm, s[j]);
        tm = fmaxf(tm, __shfl_xor_sync(0xffffffffu, tm, 1));
        tm = fmaxf(tm, __shfl_xor_sync(0xffffffffu, tm, 2));
        const float nm = fmaxf(m, tm);
        const float corr = __expf(m - nm);
        float ps = 0.f;
        #pragma unroll
        for (int j = 0; j < 8; j++) {
            const float p = __expf(s[j] - nm);
            sP[r * PST + qd * 8 + j] = p;
            ps += p;
        }
        ps += __shfl_xor_sync(0xffffffffu, ps, 1);
        ps += __shfl_xor_sync(0xffffffffu, ps, 2);
        l = l * corr + ps;
        m = nm;
        #pragma unroll
        for (int i = 0; i < 4; i++) {
            acc[i].x *= corr; acc[i].y *= corr; acc[i].z *= corr; acc[i].w *= corr;
        }
        __syncwarp();   // P row written only by this warp's 4-thread group

        // accumulate O += P @ V  (16 cols per thread)
        #pragma unroll
        for (int c = 0; c < KT; c++) {
            const float pv = sP[r * PST + c];
            const float4* v4 = (const float4*)&sV[c * KST + qd * 16];
            #pragma unroll
            for (int i = 0; i < 4; i++) {
                const float4 vv = v4[i];
                acc[i].x += pv * vv.x; acc[i].y += pv * vv.y;
                acc[i].z += pv * vv.z; acc[i].w += pv * vv.w;
            }
        }
        __syncthreads();   // protect sK/sV before next tile load
    }

    const float inv = 1.0f / l;
    float* Ob = O + base + (size_t)(q0 + r) * EMB + qd * 16;
    #pragma unroll
    for (int i = 0; i < 4; i++) {
        float4 o = acc[i];
        o.x *= inv; o.y *= inv; o.z *= inv; o.w *= inv;
        ((float4*)Ob)[i] = o;
    }
}

// ---------------------------------------------------------------------------
// Launch
// ---------------------------------------------------------------------------
extern "C" void kernel_launch(void* const* d_in, const int* in_sizes, int n_in,
                              void* d_out, int out_size)
{
    const float* x    = (const float*)d_in[0];
    const float* ln1g = (const float*)d_in[1];
    const float* ln1b = (const float*)d_in[2];
    const float* ln2g = (const float*)d_in[3];
    const float* ln2b = (const float*)d_in[4];
    const float* Wq   = (const float*)d_in[5];
    const float* bq   = (const float*)d_in[6];
    const float* Wk   = (const float*)d_in[7];
    const float* bk   = (const float*)d_in[8];
    const float* Wv   = (const float*)d_in[9];
    const float* bv   = (const float*)d_in[10];
    const float* Wo   = (const float*)d_in[11];
    const float* bo   = (const float*)d_in[12];
    const float* W1   = (const float*)d_in[13];
    const float* b1   = (const float*)d_in[14];
    const float* W2   = (const float*)d_in[15];
    const float* b2   = (const float*)d_in[16];
    float* out = (float*)d_out;

    float *xn, *q, *k, *v, *att, *x2, *xn2, *hb;
    cudaGetSymbolAddress((void**)&xn,  g_xn);
    cudaGetSymbolAddress((void**)&q,   g_q);
    cudaGetSymbolAddress((void**)&k,   g_k);
    cudaGetSymbolAddress((void**)&v,   g_v);
    cudaGetSymbolAddress((void**)&att, g_att);
    cudaGetSymbolAddress((void**)&x2,  g_x2);
    cudaGetSymbolAddress((void**)&xn2, g_xn2);
    cudaGetSymbolAddress((void**)&hb,  g_h);

    const dim3 blk(256);
    const dim3 gEmb(EMB / 128, MTOT / 128);    // N=1024
    const dim3 gMlp(MLPH / 128, MTOT / 128);   // N=4096
    const dim3 gAtt(SEQ / QT, BATCH * HEADS);

    // 1. LN1
    ln_kernel<<<MTOT, blk>>>(x, ln1g, ln1b, xn);
    // 2. QKV projections
    sgemm_kernel<0><<<gEmb, blk>>>(xn, Wq, bq, nullptr, q, MTOT, EMB, EMB);
    sgemm_kernel<0><<<gEmb, blk>>>(xn, Wk, bk, nullptr, k, MTOT, EMB, EMB);
    sgemm_kernel<0><<<gEmb, blk>>>(xn, Wv, bv, nullptr, v, MTOT, EMB, EMB);
    // 3. Attention
    attn_kernel<<<gAtt, blk>>>(q, k, v, att);
    // 4. Output projection + residual
    sgemm_kernel<2><<<gEmb, blk>>>(att, Wo, bo, x, x2, MTOT, EMB, EMB);
    // 5. LN2
    ln_kernel<<<MTOT, blk>>>(x2, ln2g, ln2b, xn2);
    // 6. MLP up + ReLU
    sgemm_kernel<1><<<gMlp, blk>>>(xn2, W1, b1, nullptr, hb, MTOT, MLPH, EMB);
    // 7. MLP down + residual -> output
    sgemm_kernel<2><<<gEmb, blk>>>(hb, W2, b2, x2, out, MTOT, EMB, MLPH);
}

// round 3
// speedup vs baseline: 2.2862x; 2.2862x over previous
#include <cuda_runtime.h>
#include <cuda_bf16.h>
#include <cstdint>

// ---------------------------------------------------------------------------
// Problem constants
// ---------------------------------------------------------------------------
#define BATCH 2
#define SEQ   2048
#define EMB   1024
#define HEADS 16
#define HDIM  64
#define MLPH  4096
#define MTOT  (BATCH * SEQ)   // 4096 rows

// ---------------------------------------------------------------------------
// Scratch (device globals: allocation-free)
// ---------------------------------------------------------------------------
__device__ float g_xn [MTOT * EMB];
__device__ float g_q  [MTOT * EMB];
__device__ float g_k  [MTOT * EMB];
__device__ float g_v  [MTOT * EMB];
__device__ float g_att[MTOT * EMB];
__device__ float g_x2 [MTOT * EMB];
__device__ float g_xn2[MTOT * EMB];
__device__ float g_h  [MTOT * MLPH];

// ---------------------------------------------------------------------------
// LayerNorm: one block per row of 1024, 256 threads, float4
// ---------------------------------------------------------------------------
__global__ __launch_bounds__(256) void ln_kernel(
    const float* __restrict__ x, const float* __restrict__ g,
    const float* __restrict__ b, float* __restrict__ y)
{
    int row = blockIdx.x;
    int tid = threadIdx.x;
    const float4 v = ((const float4*)(x + (size_t)row * EMB))[tid];

    float s  = v.x + v.y + v.z + v.w;
    float ss = v.x * v.x + v.y * v.y + v.z * v.z + v.w * v.w;
    #pragma unroll
    for (int o = 16; o; o >>= 1) {
        s  += __shfl_xor_sync(0xffffffffu, s,  o);
        ss += __shfl_xor_sync(0xffffffffu, ss, o);
    }
    __shared__ float rs[8], rss[8];
    int w = tid >> 5, lane = tid & 31;
    if (lane == 0) { rs[w] = s; rss[w] = ss; }
    __syncthreads();
    s = 0.f; ss = 0.f;
    #pragma unroll
    for (int i = 0; i < 8; i++) { s += rs[i]; ss += rss[i]; }

    const float mean = s * (1.0f / EMB);
    const float var  = ss * (1.0f / EMB) - mean * mean;
    const float rstd = rsqrtf(var + 1e-5f);

    const float4 gv = ((const float4*)g)[tid];
    const float4 bv = ((const float4*)b)[tid];
    float4 o;
    o.x = (v.x - mean) * rstd * gv.x + bv.x;
    o.y = (v.y - mean) * rstd * gv.y + bv.y;
    o.z = (v.z - mean) * rstd * gv.z + bv.z;
    o.w = (v.w - mean) * rstd * gv.w + bv.w;
    ((float4*)(y + (size_t)row * EMB))[tid] = o;
}

// ---------------------------------------------------------------------------
// SGEMM body: C = A[MxK] @ B[KxN] + bias (+ residual / relu)
// 128x128 tile, BK=16, 256 threads, 8x8 per thread, register prefetch.
// EPI: 0 = bias, 1 = bias+relu, 2 = bias+residual
// ---------------------------------------------------------------------------
template<int EPI>
__device__ __forceinline__ void sgemm_body(
    const float* __restrict__ A, const float* __restrict__ B,
    const float* __restrict__ bias, const float* __restrict__ R,
    float* __restrict__ C, int M, int N, int K, int m0, int n0,
    float* As, float* Bs)
{
    const int tid = threadIdx.x;
    const int tx = tid & 15;
    const int ty = tid >> 4;

    const int i0 = tid, i1 = tid + 256;
    const int ar0 = i0 >> 2, ac0 = (i0 & 3) * 4;
    const int ar1 = i1 >> 2, ac1 = (i1 & 3) * 4;
    const int br0 = i0 >> 5, bc0 = (i0 & 31) * 4;
    const int br1 = i1 >> 5, bc1 = (i1 & 31) * 4;

    const float* Ab = A + (size_t)m0 * K;
    const float* Bb = B + n0;

    float4 pa0 = *(const float4*)(Ab + (size_t)ar0 * K + ac0);
    float4 pa1 = *(const float4*)(Ab + (size_t)ar1 * K + ac1);
    float4 pb0 = *(const float4*)(Bb + (size_t)br0 * N + bc0);
    float4 pb1 = *(const float4*)(Bb + (size_t)br1 * N + bc1);

    float acc[8][8];
    #pragma unroll
    for (int i = 0; i < 8; i++)
        #pragma unroll
        for (int j = 0; j < 8; j++) acc[i][j] = 0.f;

    for (int k0 = 0; k0 < K; k0 += 16) {
        As[(ac0 + 0) * 128 + ar0] = pa0.x;
        As[(ac0 + 1) * 128 + ar0] = pa0.y;
        As[(ac0 + 2) * 128 + ar0] = pa0.z;
        As[(ac0 + 3) * 128 + ar0] = pa0.w;
        As[(ac1 + 0) * 128 + ar1] = pa1.x;
        As[(ac1 + 1) * 128 + ar1] = pa1.y;
        As[(ac1 + 2) * 128 + ar1] = pa1.z;
        As[(ac1 + 3) * 128 + ar1] = pa1.w;
        *(float4*)&Bs[br0 * 128 + bc0] = pb0;
        *(float4*)&Bs[br1 * 128 + bc1] = pb1;
        __syncthreads();

        if (k0 + 16 < K) {
            pa0 = *(const float4*)(Ab + (size_t)ar0 * K + (k0 + 16) + ac0);
            pa1 = *(const float4*)(Ab + (size_t)ar1 * K + (k0 + 16) + ac1);
            pb0 = *(const float4*)(Bb + (size_t)(k0 + 16 + br0) * N + bc0);
            pb1 = *(const float4*)(Bb + (size_t)(k0 + 16 + br1) * N + bc1);
        }

        #pragma unroll
        for (int k = 0; k < 16; k++) {
            float a[8], bb[8];
            *(float4*)&a[0]  = *(const float4*)&As[k * 128 + ty * 8];
            *(float4*)&a[4]  = *(const float4*)&As[k * 128 + ty * 8 + 4];
            *(float4*)&bb[0] = *(const float4*)&Bs[k * 128 + tx * 8];
            *(float4*)&bb[4] = *(const float4*)&Bs[k * 128 + tx * 8 + 4];
            #pragma unroll
            for (int i = 0; i < 8; i++)
                #pragma unroll
                for (int j = 0; j < 8; j++)
                    acc[i][j] += a[i] * bb[j];
        }
        __syncthreads();
    }

    const int gn = n0 + tx * 8;
    float4 bv0 = *(const float4*)(bias + gn);
    float4 bv1 = *(const float4*)(bias + gn + 4);
    #pragma unroll
    for (int i = 0; i < 8; i++) {
        const int gm = m0 + ty * 8 + i;
        float4 o0, o1;
        o0.x = acc[i][0] + bv0.x; o0.y = acc[i][1] + bv0.y;
        o0.z = acc[i][2] + bv0.z; o0.w = acc[i][3] + bv0.w;
        o1.x = acc[i][4] + bv1.x; o1.y = acc[i][5] + bv1.y;
        o1.z = acc[i][6] + bv1.z; o1.w = acc[i][7] + bv1.w;
        if (EPI == 1) {
            o0.x = fmaxf(o0.x, 0.f); o0.y = fmaxf(o0.y, 0.f);
            o0.z = fmaxf(o0.z, 0.f); o0.w = fmaxf(o0.w, 0.f);
            o1.x = fmaxf(o1.x, 0.f); o1.y = fmaxf(o1.y, 0.f);
            o1.z = fmaxf(o1.z, 0.f); o1.w = fmaxf(o1.w, 0.f);
        }
        if (EPI == 2) {
            const float4 r0 = *(const float4*)(R + (size_t)gm * N + gn);
            const float4 r1 = *(const float4*)(R + (size_t)gm * N + gn + 4);
            o0.x += r0.x; o0.y += r0.y; o0.z += r0.z; o0.w += r0.w;
            o1.x += r1.x; o1.y += r1.y; o1.z += r1.z; o1.w += r1.w;
        }
        *(float4*)(C + (size_t)gm * N + gn)     = o0;
        *(float4*)(C + (size_t)gm * N + gn + 4) = o1;
    }
}

template<int EPI>
__global__ __launch_bounds__(256, 1) void sgemm_kernel(
    const float* __restrict__ A, const float* __restrict__ B,
    const float* __restrict__ bias, const float* __restrict__ R,
    float* __restrict__ C, int M, int N, int K)
{
    __shared__ float As[16 * 128];
    __shared__ float Bs[16 * 128];
    sgemm_body<EPI>(A, B, bias, R, C, M, N, K,
                    blockIdx.y * 128, blockIdx.x * 128, As, Bs);
}

// Fused QKV: grid.z in {0,1,2} selects weight/bias/output triple.
__global__ __launch_bounds__(256, 1) void qkv_kernel(
    const float* __restrict__ A,
    const float* __restrict__ B0, const float* __restrict__ B1, const float* __restrict__ B2,
    const float* __restrict__ b0, const float* __restrict__ b1, const float* __restrict__ b2,
    float* __restrict__ C0, float* __restrict__ C1, float* __restrict__ C2)
{
    __shared__ float As[16 * 128];
    __shared__ float Bs[16 * 128];
    const float* B = (blockIdx.z == 0) ? B0 : (blockIdx.z == 1) ? B1 : B2;
    const float* bb = (blockIdx.z == 0) ? b0 : (blockIdx.z == 1) ? b1 : b2;
    float* C = (blockIdx.z == 0) ? C0 : (blockIdx.z == 1) ? C1 : C2;
    sgemm_body<0>(A, B, bb, nullptr, C, MTOT, EMB, EMB,
                  blockIdx.y * 128, blockIdx.x * 128, As, Bs);
}

// ---------------------------------------------------------------------------
// Flash-attention v2 (fp32, online softmax, register-blocked GEMM phases)
// grid = (SEQ/128, BATCH*HEADS), 256 threads, 100 KB dynamic smem.
// Thread (tx=tid&15, ty=tid>>4): owns 8 q-rows (ty*8..) and
//   S phase:  4 key cols (tx*4..) of the 64-key tile
//   PV phase: 4 dh  cols (tx*4..)
// smem: sQt [64 d][132]   Q transposed (d-major), q rows 0..127
//       sKt [64 d][68]    K transposed (d-major), keys 0..63
//       sV  [64 key][68]  V natural (key-major)
//       sPt [64 key][132] P transposed (key-major), q rows 0..127
// ---------------------------------------------------------------------------
#define AQT 128
#define AKT 64
#define QTS 132
#define KVS 68
#define ATT_SMEM ((64*QTS + 64*KVS + 64*KVS + 64*QTS) * 4)  // 102400 B

__global__ __launch_bounds__(256, 1) void attn2_kernel(
    const float* __restrict__ Q, const float* __restrict__ Km,
    const float* __restrict__ Vm, float* __restrict__ O)
{
    extern __shared__ float sm[];
    float* sQt = sm;
    float* sKt = sQt + 64 * QTS;
    float* sV  = sKt + 64 * KVS;
    float* sPt = sV  + 64 * KVS;

    const int bh = blockIdx.y;
    const int b  = bh / HEADS;
    const int h  = bh % HEADS;
    const int q0 = blockIdx.x * AQT;
    const int tid = threadIdx.x;
    const int tx = tid & 15;
    const int ty = tid >> 4;

    const size_t base = ((size_t)b * SEQ) * EMB + (size_t)h * HDIM;
    const float* Qb = Q  + base;
    const float* Kb = Km + base;
    const float* Vb = Vm + base;

    // Q tile load, pre-scaled, stored transposed (d-major): 2048 float4
    #pragma unroll
    for (int t = 0; t < 8; t++) {
        int idx = tid + t * 256;
        int qr = idx >> 4, c4 = (idx & 15) * 4;
        float4 v = *(const float4*)(Qb + (size_t)(q0 + qr) * EMB + c4);
        sQt[(c4 + 0) * QTS + qr] = v.x * 0.125f;
        sQt[(c4 + 1) * QTS + qr] = v.y * 0.125f;
        sQt[(c4 + 2) * QTS + qr] = v.z * 0.125f;
        sQt[(c4 + 3) * QTS + qr] = v.w * 0.125f;
    }

    // softmax state + O accumulators
    float m[8], l[8], o[8][4];
    #pragma unroll
    for (int i = 0; i < 8; i++) {
        m[i] = -1e30f; l[i] = 0.f;
        #pragma unroll
        for (int j = 0; j < 4; j++) o[i][j] = 0.f;
    }

    // K/V prefetch registers (4 float4 each; 1024 float4 per tile)
    const int kr0 = tid >> 4;          // key row within tile segment
    const int kc4 = (tid & 15) * 4;    // d offset
    float4 pk[4], pv[4];
    #pragma unroll
    for (int t = 0; t < 4; t++) {
        size_t goff = (size_t)(kr0 + t * 16) * EMB + kc4;
        pk[t] = *(const float4*)(Kb + goff);
        pv[t] = *(const float4*)(Vb + goff);
    }

    for (int kt = 0; kt < SEQ / AKT; kt++) {
        // commit prefetched K (transposed) and V (natural) to smem
        #pragma unroll
        for (int t = 0; t < 4; t++) {
            int kr = kr0 + t * 16;
            sKt[(kc4 + 0) * KVS + kr] = pk[t].x;
            sKt[(kc4 + 1) * KVS + kr] = pk[t].y;
            sKt[(kc4 + 2) * KVS + kr] = pk[t].z;
            sKt[(kc4 + 3) * KVS + kr] = pk[t].w;
            *(float4*)&sV[kr * KVS + kc4] = pv[t];
        }
        __syncthreads();

        if (kt + 1 < SEQ / AKT) {  // prefetch next tile
            const size_t tb = (size_t)(kt + 1) * AKT * EMB;
            #pragma unroll
            for (int t = 0; t < 4; t++) {
                size_t goff = tb + (size_t)(kr0 + t * 16) * EMB + kc4;
                pk[t] = *(const float4*)(Kb + goff);
                pv[t] = *(const float4*)(Vb + goff);
            }
        }

        // ---- S = Q @ K^T : s[8 rows][4 keys]
        float s[8][4];
        #pragma unroll
        for (int i = 0; i < 8; i++)
            #pragma unroll
            for (int j = 0; j < 4; j++) s[i][j] = 0.f;

        #pragma unroll 8
        for (int k = 0; k < HDIM; k++) {
            float a[8], bb[4];
            *(float4*)&a[0] = *(const float4*)&sQt[k * QTS + ty * 8];
            *(float4*)&a[4] = *(const float4*)&sQt[k * QTS + ty * 8 + 4];
            *(float4*)&bb[0] = *(const float4*)&sKt[k * KVS + tx * 4];
            #pragma unroll
            for (int i = 0; i < 8; i++)
                #pragma unroll
                for (int j = 0; j < 4; j++)
                    s[i][j] += a[i] * bb[j];
        }

        // ---- online softmax (row state shared by 16 tx threads via shfl)
        #pragma unroll
        for (int i = 0; i < 8; i++) {
            float tm = fmaxf(fmaxf(s[i][0], s[i][1]), fmaxf(s[i][2], s[i][3]));
            tm = fmaxf(tm, __shfl_xor_sync(0xffffffffu, tm, 1));
            tm = fmaxf(tm, __shfl_xor_sync(0xffffffffu, tm, 2));
            tm = fmaxf(tm, __shfl_xor_sync(0xffffffffu, tm, 4));
            tm = fmaxf(tm, __shfl_xor_sync(0xffffffffu, tm, 8));
            const float nm = fmaxf(m[i], tm);
            const float corr = __expf(m[i] - nm);
            float ps = 0.f;
            #pragma unroll
            for (int j = 0; j < 4; j++) {
                const float p = __expf(s[i][j] - nm);
                s[i][j] = p;
                ps += p;
            }
            ps += __shfl_xor_sync(0xffffffffu, ps, 1);
            ps += __shfl_xor_sync(0xffffffffu, ps, 2);
            ps += __shfl_xor_sync(0xffffffffu, ps, 4);
            ps += __shfl_xor_sync(0xffffffffu, ps, 8);
            l[i] = l[i] * corr + ps;
            m[i] = nm;
            o[i][0] *= corr; o[i][1] *= corr; o[i][2] *= corr; o[i][3] *= corr;
        }

        // write P transposed: key-major [key][qrow]
        #pragma unroll
        for (int j = 0; j < 4; j++) {
            float* dst = &sPt[(tx * 4 + j) * QTS + ty * 8];
            dst[0] = s[0][j]; dst[1] = s[1][j]; dst[2] = s[2][j]; dst[3] = s[3][j];
            dst[4] = s[4][j]; dst[5] = s[5][j]; dst[6] = s[6][j]; dst[7] = s[7][j];
        }
        __syncthreads();

        // ---- O += P @ V : o[8 rows][4 dh cols]
        #pragma unroll 8
        for (int k = 0; k < AKT; k++) {
            float a[8], bb[4];
            *(float4*)&a[0] = *(const float4*)&sPt[k * QTS + ty * 8];
            *(float4*)&a[4] = *(const float4*)&sPt[k * QTS + ty * 8 + 4];
            *(float4*)&bb[0] = *(const float4*)&sV[k * KVS + tx * 4];
            #pragma unroll
            for (int i = 0; i < 8; i++)
                #pragma unroll
                for (int j = 0; j < 4; j++)
                    o[i][j] += a[i] * bb[j];
        }
        __syncthreads();   // protect sKt/sV/sPt before next commit
    }

    // epilogue
    #pragma unroll
    for (int i = 0; i < 8; i++) {
        const float inv = 1.0f / l[i];
        float4 ov;
        ov.x = o[i][0] * inv; ov.y = o[i][1] * inv;
        ov.z = o[i][2] * inv; ov.w = o[i][3] * inv;
        *(float4*)(O + base + (size_t)(q0 + ty * 8 + i) * EMB + tx * 4) = ov;
    }
}

// ---------------------------------------------------------------------------
// Launch
// ---------------------------------------------------------------------------
extern "C" void kernel_launch(void* const* d_in, const int* in_sizes, int n_in,
                              void* d_out, int out_size)
{
    const float* x    = (const float*)d_in[0];
    const float* ln1g = (const float*)d_in[1];
    const float* ln1b = (const float*)d_in[2];
    const float* ln2g = (const float*)d_in[3];
    const float* ln2b = (const float*)d_in[4];
    const float* Wq   = (const float*)d_in[5];
    const float* bq   = (const float*)d_in[6];
    const float* Wk   = (const float*)d_in[7];
    const float* bk   = (const float*)d_in[8];
    const float* Wv   = (const float*)d_in[9];
    const float* bv   = (const float*)d_in[10];
    const float* Wo   = (const float*)d_in[11];
    const float* bo   = (const float*)d_in[12];
    const float* W1   = (const float*)d_in[13];
    const float* b1   = (const float*)d_in[14];
    const float* W2   = (const float*)d_in[15];
    const float* b2   = (const float*)d_in[16];
    float* out = (float*)d_out;

    float *xn, *q, *k, *v, *att, *x2, *xn2, *hb;
    cudaGetSymbolAddress((void**)&xn,  g_xn);
    cudaGetSymbolAddress((void**)&q,   g_q);
    cudaGetSymbolAddress((void**)&k,   g_k);
    cudaGetSymbolAddress((void**)&v,   g_v);
    cudaGetSymbolAddress((void**)&att, g_att);
    cudaGetSymbolAddress((void**)&x2,  g_x2);
    cudaGetSymbolAddress((void**)&xn2, g_xn2);
    cudaGetSymbolAddress((void**)&hb,  g_h);

    cudaFuncSetAttribute(attn2_kernel,
                         cudaFuncAttributeMaxDynamicSharedMemorySize, ATT_SMEM);

    const dim3 blk(256);
    const dim3 gQKV(EMB / 128, MTOT / 128, 3);
    const dim3 gEmb(EMB / 128, MTOT / 128);
    const dim3 gMlp(MLPH / 128, MTOT / 128);
    const dim3 gAtt(SEQ / AQT, BATCH * HEADS);

    // 1. LN1
    ln_kernel<<<MTOT, blk>>>(x, ln1g, ln1b, xn);
    // 2. QKV projections (fused launch)
    qkv_kernel<<<gQKV, blk>>>(xn, Wq, Wk, Wv, bq, bk, bv, q, k, v);
    // 3. Attention
    attn2_kernel<<<gAtt, blk, ATT_SMEM>>>(q, k, v, att);
    // 4. Output projection + residual
    sgemm_kernel<2><<<gEmb, blk>>>(att, Wo, bo, x, x2, MTOT, EMB, EMB);
    // 5. LN2
    ln_kernel<<<MTOT, blk>>>(x2, ln2g, ln2b, xn2);
    // 6. MLP up + ReLU
    sgemm_kernel<1><<<gMlp, blk>>>(xn2, W1, b1, nullptr, hb, MTOT, MLPH, EMB);
    // 7. MLP down + residual -> output
    sgemm_kernel<2><<<gEmb, blk>>>(hb, W2, b2, x2, out, MTOT, EMB, MLPH);
}

// round 6
// speedup vs baseline: 4.5620x; 1.9954x over previous
#include <cuda_runtime.h>
#include <cuda_bf16.h>
#include <cstdint>

// ---------------------------------------------------------------------------
// Problem constants
// ---------------------------------------------------------------------------
#define BATCH 2
#define SEQ   2048
#define EMB   1024
#define HEADS 16
#define HDIM  64
#define MLPH  4096
#define MTOT  (BATCH * SEQ)   // 4096 rows

// ---------------------------------------------------------------------------
// Scratch (device globals: allocation-free)
// ---------------------------------------------------------------------------
__device__ float g_xn [MTOT * EMB];
__device__ float g_q  [MTOT * EMB];
__device__ float g_k  [MTOT * EMB];
__device__ float g_v  [MTOT * EMB];
__device__ float g_att[MTOT * EMB];
__device__ float g_x2 [MTOT * EMB];
__device__ float g_xn2[MTOT * EMB];
__device__ float g_h  [MTOT * MLPH];

// ---------------------------------------------------------------------------
// LayerNorm: one block per row of 1024, 256 threads, float4
// ---------------------------------------------------------------------------
__global__ __launch_bounds__(256) void ln_kernel(
    const float* __restrict__ x, const float* __restrict__ g,
    const float* __restrict__ b, float* __restrict__ y)
{
    int row = blockIdx.x;
    int tid = threadIdx.x;
    const float4 v = ((const float4*)(x + (size_t)row * EMB))[tid];

    float s  = v.x + v.y + v.z + v.w;
    float ss = v.x * v.x + v.y * v.y + v.z * v.z + v.w * v.w;
    #pragma unroll
    for (int o = 16; o; o >>= 1) {
        s  += __shfl_xor_sync(0xffffffffu, s,  o);
        ss += __shfl_xor_sync(0xffffffffu, ss, o);
    }
    __shared__ float rs[8], rss[8];
    int w = tid >> 5, lane = tid & 31;
    if (lane == 0) { rs[w] = s; rss[w] = ss; }
    __syncthreads();
    s = 0.f; ss = 0.f;
    #pragma unroll
    for (int i = 0; i < 8; i++) { s += rs[i]; ss += rss[i]; }

    const float mean = s * (1.0f / EMB);
    const float var  = ss * (1.0f / EMB) - mean * mean;
    const float rstd = rsqrtf(var + 1e-5f);

    const float4 gv = ((const float4*)g)[tid];
    const float4 bv = ((const float4*)b)[tid];
    float4 o;
    o.x = (v.x - mean) * rstd * gv.x + bv.x;
    o.y = (v.y - mean) * rstd * gv.y + bv.y;
    o.z = (v.z - mean) * rstd * gv.z + bv.z;
    o.w = (v.w - mean) * rstd * gv.w + bv.w;
    ((float4*)(y + (size_t)row * EMB))[tid] = o;
}

// ---------------------------------------------------------------------------
// TF32 tensor-core GEMM: C = A[MxK] @ B[KxN] + bias (+ residual / relu)
// CTA 128x256, BK=16, 256 threads (8 warps), warp tile 64x64 (m16n8k8 mma).
// Warps: 2 along M x 4 along N. Per warp: 4 m-tiles x 8 n-tiles.
// Smem strides 136/264 (mod 32 == 8) -> conflict-free fragment LDS.
// EPI: 0 = bias, 1 = bias+relu, 2 = bias+residual
// Requires M%128==0, N%256==0, K%16==0.
// ---------------------------------------------------------------------------
#define BM 128
#define BN 256
#define BK 16
#define AST 136
#define BST 264

__device__ __forceinline__ uint32_t f2tf(float f) {
    uint32_t u;
    asm("cvt.rna.tf32.f32 %0, %1;" : "=r"(u) : "f"(f));
    return u;
}

__device__ __forceinline__ void mma_tf32(
    float* c, uint32_t a0, uint32_t a1, uint32_t a2, uint32_t a3,
    uint32_t b0, uint32_t b1)
{
    asm volatile(
        "mma.sync.aligned.m16n8k8.row.col.f32.tf32.tf32.f32 "
        "{%0,%1,%2,%3}, {%4,%5,%6,%7}, {%8,%9}, {%0,%1,%2,%3};"
        : "+f"(c[0]), "+f"(c[1]), "+f"(c[2]), "+f"(c[3])
        : "r"(a0), "r"(a1), "r"(a2), "r"(a3), "r"(b0), "r"(b1));
}

template<int EPI>
__device__ __forceinline__ void tgemm_body(
    const float* __restrict__ A, const float* __restrict__ B,
    const float* __restrict__ bias, const float* __restrict__ R,
    float* __restrict__ C, int M, int N, int K, int m0, int n0,
    uint32_t* As, uint32_t* Bs)
{
    const int tid  = threadIdx.x;
    const int warp = tid >> 5;
    const int lane = tid & 31;
    const int gr   = lane >> 2;    // 0..7
    const int gc   = lane & 3;     // 0..3
    const int wm   = (warp & 1) * 64;
    const int wn   = (warp >> 1) * 64;

    // A loader: 128x16 tile = 512 float4, 2/thread
    const int ar0 = tid >> 2,           ac0 = (tid & 3) * 4;
    const int ar1 = (tid + 256) >> 2,   ac1 = ((tid + 256) & 3) * 4;
    // B loader: 16x256 tile = 1024 float4, 4/thread
    const int br[4] = { tid >> 6, (tid + 256) >> 6, (tid + 512) >> 6, (tid + 768) >> 6 };
    const int bc    = (tid & 63) * 4;

    const float* Ab = A + (size_t)m0 * K;
    const float* Bb = B + n0;

    float4 pa0 = *(const float4*)(Ab + (size_t)ar0 * K + ac0);
    float4 pa1 = *(const float4*)(Ab + (size_t)ar1 * K + ac1);
    float4 pb[4];
    #pragma unroll
    for (int t = 0; t < 4; t++)
        pb[t] = *(const float4*)(Bb + (size_t)br[t] * N + bc);

    float acc[4][8][4];
    #pragma unroll
    for (int mt = 0; mt < 4; mt++)
        #pragma unroll
        for (int nt = 0; nt < 8; nt++)
            #pragma unroll
            for (int r = 0; r < 4; r++) acc[mt][nt][r] = 0.f;

    for (int k0 = 0; k0 < K; k0 += BK) {
        // commit (convert to tf32 at store time)
        As[(ac0 + 0) * AST + ar0] = f2tf(pa0.x);
        As[(ac0 + 1) * AST + ar0] = f2tf(pa0.y);
        As[(ac0 + 2) * AST + ar0] = f2tf(pa0.z);
        As[(ac0 + 3) * AST + ar0] = f2tf(pa0.w);
        As[(ac1 + 0) * AST + ar1] = f2tf(pa1.x);
        As[(ac1 + 1) * AST + ar1] = f2tf(pa1.y);
        As[(ac1 + 2) * AST + ar1] = f2tf(pa1.z);
        As[(ac1 + 3) * AST + ar1] = f2tf(pa1.w);
        #pragma unroll
        for (int t = 0; t < 4; t++) {
            uint4 u;
            u.x = f2tf(pb[t].x); u.y = f2tf(pb[t].y);
            u.z = f2tf(pb[t].z); u.w = f2tf(pb[t].w);
            *(uint4*)&Bs[br[t] * BST + bc] = u;
        }
        __syncthreads();

        if (k0 + BK < K) {  // prefetch next tile
            pa0 = *(const float4*)(Ab + (size_t)ar0 * K + (k0 + BK) + ac0);
            pa1 = *(const float4*)(Ab + (size_t)ar1 * K + (k0 + BK) + ac1);
            #pragma unroll
            for (int t = 0; t < 4; t++)
                pb[t] = *(const float4*)(Bb + (size_t)(k0 + BK + br[t]) * N + bc);
        }

        #pragma unroll
        for (int ks = 0; ks < BK; ks += 8) {
            uint32_t af[4][4];
            #pragma unroll
            for (int mt = 0; mt < 4; mt++) {
                const int m = wm + mt * 16 + gr;
                const int ka = ks + gc;
                af[mt][0] = As[ka * AST + m];
                af[mt][1] = As[ka * AST + m + 8];
                af[mt][2] = As[(ka + 4) * AST + m];
                af[mt][3] = As[(ka + 4) * AST + m + 8];
            }
            uint32_t bf[8][2];
            #pragma unroll
            for (int nt = 0; nt < 8; nt++) {
                const int n = wn + nt * 8 + gr;
                bf[nt][0] = Bs[(ks + gc) * BST + n];
                bf[nt][1] = Bs[(ks + gc + 4) * BST + n];
            }
            #pragma unroll
            for (int mt = 0; mt < 4; mt++)
                #pragma unroll
                for (int nt = 0; nt < 8; nt++)
                    mma_tf32(acc[mt][nt], af[mt][0], af[mt][1], af[mt][2], af[mt][3],
                             bf[nt][0], bf[nt][1]);
        }
        __syncthreads();
    }

    // epilogue: each thread owns rows (gr, gr+8) and 2 cols per (mt,nt)
    float2 bv[8];
    #pragma unroll
    for (int nt = 0; nt < 8; nt++)
        bv[nt] = *(const float2*)(bias + n0 + wn + nt * 8 + gc * 2);

    #pragma unroll
    for (int mt = 0; mt < 4; mt++) {
        const int gm = m0 + wm + mt * 16 + gr;
        #pragma unroll
        for (int nt = 0; nt < 8; nt++) {
            const int gn = n0 + wn + nt * 8 + gc * 2;
            float2 o0, o1;
            o0.x = acc[mt][nt][0] + bv[nt].x;
            o0.y = acc[mt][nt][1] + bv[nt].y;
            o1.x = acc[mt][nt][2] + bv[nt].x;
            o1.y = acc[mt][nt][3] + bv[nt].y;
            if (EPI == 1) {
                o0.x = fmaxf(o0.x, 0.f); o0.y = fmaxf(o0.y, 0.f);
                o1.x = fmaxf(o1.x, 0.f); o1.y = fmaxf(o1.y, 0.f);
            }
            if (EPI == 2) {
                const float2 r0 = *(const float2*)(R + (size_t)gm * N + gn);
                const float2 r1 = *(const float2*)(R + (size_t)(gm + 8) * N + gn);
                o0.x += r0.x; o0.y += r0.y;
                o1.x += r1.x; o1.y += r1.y;
            }
            *(float2*)(C + (size_t)gm * N + gn)       = o0;
            *(float2*)(C + (size_t)(gm + 8) * N + gn) = o1;
        }
    }
}

template<int EPI>
__global__ __launch_bounds__(256, 1) void tgemm_kernel(
    const float* __restrict__ A, const float* __restrict__ B,
    const float* __restrict__ bias, const float* __restrict__ R,
    float* __restrict__ C, int M, int N, int K)
{
    __shared__ uint32_t As[BK * AST];
    __shared__ uint32_t Bs[BK * BST];
    tgemm_body<EPI>(A, B, bias, R, C, M, N, K,
                    blockIdx.y * BM, blockIdx.x * BN, As, Bs);
}

// Fused QKV: grid.z in {0,1,2} selects weight/bias/output triple.
__global__ __launch_bounds__(256, 1) void qkv_kernel(
    const float* __restrict__ A,
    const float* __restrict__ B0, const float* __restrict__ B1, const float* __restrict__ B2,
    const float* __restrict__ b0, const float* __restrict__ b1, const float* __restrict__ b2,
    float* __restrict__ C0, float* __restrict__ C1, float* __restrict__ C2)
{
    __shared__ uint32_t As[BK * AST];
    __shared__ uint32_t Bs[BK * BST];
    const float* B = (blockIdx.z == 0) ? B0 : (blockIdx.z == 1) ? B1 : B2;
    const float* bb = (blockIdx.z == 0) ? b0 : (blockIdx.z == 1) ? b1 : b2;
    float* C = (blockIdx.z == 0) ? C0 : (blockIdx.z == 1) ? C1 : C2;
    tgemm_body<0>(A, B, bb, nullptr, C, MTOT, EMB, EMB,
                  blockIdx.y * BM, blockIdx.x * BN, As, Bs);
}

// ---------------------------------------------------------------------------
// Flash-attention v2 (fp32, online softmax, register-blocked GEMM phases)
// grid = (SEQ/128, BATCH*HEADS), 256 threads, 100 KB dynamic smem.
// ---------------------------------------------------------------------------
#define AQT 128
#define AKT 64
#define QTS 132
#define KVS 68
#define ATT_SMEM ((64*QTS + 64*KVS + 64*KVS + 64*QTS) * 4)  // 102400 B

__global__ __launch_bounds__(256, 1) void attn2_kernel(
    const float* __restrict__ Q, const float* __restrict__ Km,
    const float* __restrict__ Vm, float* __restrict__ O)
{
    extern __shared__ float sm[];
    float* sQt = sm;
    float* sKt = sQt + 64 * QTS;
    float* sV  = sKt + 64 * KVS;
    float* sPt = sV  + 64 * KVS;

    const int bh = blockIdx.y;
    const int b  = bh / HEADS;
    const int h  = bh % HEADS;
    const int q0 = blockIdx.x * AQT;
    const int tid = threadIdx.x;
    const int tx = tid & 15;
    const int ty = tid >> 4;

    const size_t base = ((size_t)b * SEQ) * EMB + (size_t)h * HDIM;
    const float* Qb = Q  + base;
    const float* Kb = Km + base;
    const float* Vb = Vm + base;

    #pragma unroll
    for (int t = 0; t < 8; t++) {
        int idx = tid + t * 256;
        int qr = idx >> 4, c4 = (idx & 15) * 4;
        float4 v = *(const float4*)(Qb + (size_t)(q0 + qr) * EMB + c4);
        sQt[(c4 + 0) * QTS + qr] = v.x * 0.125f;
        sQt[(c4 + 1) * QTS + qr] = v.y * 0.125f;
        sQt[(c4 + 2) * QTS + qr] = v.z * 0.125f;
        sQt[(c4 + 3) * QTS + qr] = v.w * 0.125f;
    }

    float m[8], l[8], o[8][4];
    #pragma unroll
    for (int i = 0; i < 8; i++) {
        m[i] = -1e30f; l[i] = 0.f;
        #pragma unroll
        for (int j = 0; j < 4; j++) o[i][j] = 0.f;
    }

    const int kr0 = tid >> 4;
    const int kc4 = (tid & 15) * 4;
    float4 pk[4], pv[4];
    #pragma unroll
    for (int t = 0; t < 4; t++) {
        size_t goff = (size_t)(kr0 + t * 16) * EMB + kc4;
        pk[t] = *(const float4*)(Kb + goff);
        pv[t] = *(const float4*)(Vb + goff);
    }

    for (int kt = 0; kt < SEQ / AKT; kt++) {
        #pragma unroll
        for (int t = 0; t < 4; t++) {
            int kr = kr0 + t * 16;
            sKt[(kc4 + 0) * KVS + kr] = pk[t].x;
            sKt[(kc4 + 1) * KVS + kr] = pk[t].y;
            sKt[(kc4 + 2) * KVS + kr] = pk[t].z;
            sKt[(kc4 + 3) * KVS + kr] = pk[t].w;
            *(float4*)&sV[kr * KVS + kc4] = pv[t];
        }
        __syncthreads();

        if (kt + 1 < SEQ / AKT) {
            const size_t tb = (size_t)(kt + 1) * AKT * EMB;
            #pragma unroll
            for (int t = 0; t < 4; t++) {
                size_t goff = tb + (size_t)(kr0 + t * 16) * EMB + kc4;
                pk[t] = *(const float4*)(Kb + goff);
                pv[t] = *(const float4*)(Vb + goff);
            }
        }

        float s[8][4];
        #pragma unroll
        for (int i = 0; i < 8; i++)
            #pragma unroll
            for (int j = 0; j < 4; j++) s[i][j] = 0.f;

        #pragma unroll 8
        for (int k = 0; k < HDIM; k++) {
            float a[8], bb[4];
            *(float4*)&a[0] = *(const float4*)&sQt[k * QTS + ty * 8];
            *(float4*)&a[4] = *(const float4*)&sQt[k * QTS + ty * 8 + 4];
            *(float4*)&bb[0] = *(const float4*)&sKt[k * KVS + tx * 4];
            #pragma unroll
            for (int i = 0; i < 8; i++)
                #pragma unroll
                for (int j = 0; j < 4; j++)
                    s[i][j] += a[i] * bb[j];
        }

        #pragma unroll
        for (int i = 0; i < 8; i++) {
            float tm = fmaxf(fmaxf(s[i][0], s[i][1]), fmaxf(s[i][2], s[i][3]));
            tm = fmaxf(tm, __shfl_xor_sync(0xffffffffu, tm, 1));
            tm = fmaxf(tm, __shfl_xor_sync(0xffffffffu, tm, 2));
            tm = fmaxf(tm, __shfl_xor_sync(0xffffffffu, tm, 4));
            tm = fmaxf(tm, __shfl_xor_sync(0xffffffffu, tm, 8));
            const float nm = fmaxf(m[i], tm);
            const float corr = __expf(m[i] - nm);
            float ps = 0.f;
            #pragma unroll
            for (int j = 0; j < 4; j++) {
                const float p = __expf(s[i][j] - nm);
                s[i][j] = p;
                ps += p;
            }
            ps += __shfl_xor_sync(0xffffffffu, ps, 1);
            ps += __shfl_xor_sync(0xffffffffu, ps, 2);
            ps += __shfl_xor_sync(0xffffffffu, ps, 4);
            ps += __shfl_xor_sync(0xffffffffu, ps, 8);
            l[i] = l[i] * corr + ps;
            m[i] = nm;
            o[i][0] *= corr; o[i][1] *= corr; o[i][2] *= corr; o[i][3] *= corr;
        }

        #pragma unroll
        for (int j = 0; j < 4; j++) {
            float* dst = &sPt[(tx * 4 + j) * QTS + ty * 8];
            dst[0] = s[0][j]; dst[1] = s[1][j]; dst[2] = s[2][j]; dst[3] = s[3][j];
            dst[4] = s[4][j]; dst[5] = s[5][j]; dst[6] = s[6][j]; dst[7] = s[7][j];
        }
        __syncthreads();

        #pragma unroll 8
        for (int k = 0; k < AKT; k++) {
            float a[8], bb[4];
            *(float4*)&a[0] = *(const float4*)&sPt[k * QTS + ty * 8];
            *(float4*)&a[4] = *(const float4*)&sPt[k * QTS + ty * 8 + 4];
            *(float4*)&bb[0] = *(const float4*)&sV[k * KVS + tx * 4];
            #pragma unroll
            for (int i = 0; i < 8; i++)
                #pragma unroll
                for (int j = 0; j < 4; j++)
                    o[i][j] += a[i] * bb[j];
        }
        __syncthreads();
    }

    #pragma unroll
    for (int i = 0; i < 8; i++) {
        const float inv = 1.0f / l[i];
        float4 ov;
        ov.x = o[i][0] * inv; ov.y = o[i][1] * inv;
        ov.z = o[i][2] * inv; ov.w = o[i][3] * inv;
        *(float4*)(O + base + (size_t)(q0 + ty * 8 + i) * EMB + tx * 4) = ov;
    }
}

// ---------------------------------------------------------------------------
// Launch
// ---------------------------------------------------------------------------
extern "C" void kernel_launch(void* const* d_in, const int* in_sizes, int n_in,
                              void* d_out, int out_size)
{
    const float* x    = (const float*)d_in[0];
    const float* ln1g = (const float*)d_in[1];
    const float* ln1b = (const float*)d_in[2];
    const float* ln2g = (const float*)d_in[3];
    const float* ln2b = (const float*)d_in[4];
    const float* Wq   = (const float*)d_in[5];
    const float* bq   = (const float*)d_in[6];
    const float* Wk   = (const float*)d_in[7];
    const float* bk   = (const float*)d_in[8];
    const float* Wv   = (const float*)d_in[9];
    const float* bv   = (const float*)d_in[10];
    const float* Wo   = (const float*)d_in[11];
    const float* bo   = (const float*)d_in[12];
    const float* W1   = (const float*)d_in[13];
    const float* b1   = (const float*)d_in[14];
    const float* W2   = (const float*)d_in[15];
    const float* b2   = (const float*)d_in[16];
    float* out = (float*)d_out;

    float *xn, *q, *k, *v, *att, *x2, *xn2, *hb;
    cudaGetSymbolAddress((void**)&xn,  g_xn);
    cudaGetSymbolAddress((void**)&q,   g_q);
    cudaGetSymbolAddress((void**)&k,   g_k);
    cudaGetSymbolAddress((void**)&v,   g_v);
    cudaGetSymbolAddress((void**)&att, g_att);
    cudaGetSymbolAddress((void**)&x2,  g_x2);
    cudaGetSymbolAddress((void**)&xn2, g_xn2);
    cudaGetSymbolAddress((void**)&hb,  g_h);

    cudaFuncSetAttribute(attn2_kernel,
                         cudaFuncAttributeMaxDynamicSharedMemorySize, ATT_SMEM);

    const dim3 blk(256);
    const dim3 gQKV(EMB / BN, MTOT / BM, 3);
    const dim3 gEmb(EMB / BN, MTOT / BM);
    const dim3 gMlp(MLPH / BN, MTOT / BM);
    const dim3 gAtt(SEQ / AQT, BATCH * HEADS);

    // 1. LN1
    ln_kernel<<<MTOT, blk>>>(x, ln1g, ln1b, xn);
    // 2. QKV projections (fused launch, tf32 tensor cores)
    qkv_kernel<<<gQKV, blk>>>(xn, Wq, Wk, Wv, bq, bk, bv, q, k, v);
    // 3. Attention
    attn2_kernel<<<gAtt, blk, ATT_SMEM>>>(q, k, v, att);
    // 4. Output projection + residual
    tgemm_kernel<2><<<gEmb, blk>>>(att, Wo, bo, x, x2, MTOT, EMB, EMB);
    // 5. LN2
    ln_kernel<<<MTOT, blk>>>(x2, ln2g, ln2b, xn2);
    // 6. MLP up + ReLU
    tgemm_kernel<1><<<gMlp, blk>>>(xn2, W1, b1, nullptr, hb, MTOT, MLPH, EMB);
    // 7. MLP down + residual -> output
    tgemm_kernel<2><<<gEmb, blk>>>(hb, W2, b2, x2, out, MTOT, EMB, MLPH);
}

// round 9
// speedup vs baseline: 6.3191x; 1.3852x over previous
#include <cuda_runtime.h>
#include <cuda_bf16.h>
#include <cstdint>

// ---------------------------------------------------------------------------
// Problem constants
// ---------------------------------------------------------------------------
#define BATCH 2
#define SEQ   2048
#define EMB   1024
#define HEADS 16
#define HDIM  64
#define MLPH  4096
#define MTOT  (BATCH * SEQ)   // 4096 rows

// ---------------------------------------------------------------------------
// Scratch (device globals: allocation-free)
// ---------------------------------------------------------------------------
__device__ float g_xn [MTOT * EMB];
__device__ float g_q  [MTOT * EMB];
__device__ float g_k  [MTOT * EMB];
__device__ float g_v  [MTOT * EMB];
__device__ float g_att[MTOT * EMB];
__device__ float g_x2 [MTOT * EMB];
__device__ float g_xn2[MTOT * EMB];
__device__ float g_h  [MTOT * MLPH];

// ---------------------------------------------------------------------------
// Helpers
// ---------------------------------------------------------------------------
__device__ __forceinline__ uint32_t f2tf(float f) {
    uint32_t u;
    asm("cvt.rna.tf32.f32 %0, %1;" : "=r"(u) : "f"(f));
    return u;
}
__device__ __forceinline__ float ex2(float x) {
    float r;
    asm("ex2.approx.f32 %0, %1;" : "=f"(r) : "f"(x));
    return r;
}
__device__ __forceinline__ void mma_tf32(
    float* c, uint32_t a0, uint32_t a1, uint32_t a2, uint32_t a3,
    uint32_t b0, uint32_t b1)
{
    asm volatile(
        "mma.sync.aligned.m16n8k8.row.col.f32.tf32.tf32.f32 "
        "{%0,%1,%2,%3}, {%4,%5,%6,%7}, {%8,%9}, {%0,%1,%2,%3};"
        : "+f"(c[0]), "+f"(c[1]), "+f"(c[2]), "+f"(c[3])
        : "r"(a0), "r"(a1), "r"(a2), "r"(a3), "r"(b0), "r"(b1));
}

// ---------------------------------------------------------------------------
// LayerNorm: one block per row of 1024, 256 threads, float4
// ---------------------------------------------------------------------------
__global__ __launch_bounds__(256) void ln_kernel(
    const float* __restrict__ x, const float* __restrict__ g,
    const float* __restrict__ b, float* __restrict__ y)
{
    int row = blockIdx.x;
    int tid = threadIdx.x;
    const float4 v = ((const float4*)(x + (size_t)row * EMB))[tid];

    float s  = v.x + v.y + v.z + v.w;
    float ss = v.x * v.x + v.y * v.y + v.z * v.z + v.w * v.w;
    #pragma unroll
    for (int o = 16; o; o >>= 1) {
        s  += __shfl_xor_sync(0xffffffffu, s,  o);
        ss += __shfl_xor_sync(0xffffffffu, ss, o);
    }
    __shared__ float rs[8], rss[8];
    int w = tid >> 5, lane = tid & 31;
    if (lane == 0) { rs[w] = s; rss[w] = ss; }
    __syncthreads();
    s = 0.f; ss = 0.f;
    #pragma unroll
    for (int i = 0; i < 8; i++) { s += rs[i]; ss += rss[i]; }

    const float mean = s * (1.0f / EMB);
    const float var  = ss * (1.0f / EMB) - mean * mean;
    const float rstd = rsqrtf(var + 1e-5f);

    const float4 gv = ((const float4*)g)[tid];
    const float4 bv = ((const float4*)b)[tid];
    float4 o;
    o.x = (v.x - mean) * rstd * gv.x + bv.x;
    o.y = (v.y - mean) * rstd * gv.y + bv.y;
    o.z = (v.z - mean) * rstd * gv.z + bv.z;
    o.w = (v.w - mean) * rstd * gv.w + bv.w;
    ((float4*)(y + (size_t)row * EMB))[tid] = o;
}

// ---------------------------------------------------------------------------
// TF32 tensor-core GEMM: C = A[MxK] @ B[KxN] + bias (+ residual / relu)
// CTA 128x256, BK=16, 256 threads (8 warps), warp tile 64x64 (m16n8k8 mma).
// nt-outer mma loop: b fragments transient -> lower live registers (no spill).
// EPI: 0 = bias, 1 = bias+relu, 2 = bias+residual
// ---------------------------------------------------------------------------
#define BM 128
#define BN 256
#define BK 16
#define AST 136
#define BST 264

template<int EPI>
__device__ __forceinline__ void tgemm_body(
    const float* __restrict__ A, const float* __restrict__ B,
    const float* __restrict__ bias, const float* __restrict__ R,
    float* __restrict__ C, int M, int N, int K, int m0, int n0,
    uint32_t* As, uint32_t* Bs)
{
    const int tid  = threadIdx.x;
    const int warp = tid >> 5;
    const int lane = tid & 31;
    const int gr   = lane >> 2;    // 0..7
    const int gc   = lane & 3;     // 0..3
    const int wm   = (warp & 1) * 64;
    const int wn   = (warp >> 1) * 64;

    const int ar0 = tid >> 2,           ac0 = (tid & 3) * 4;
    const int ar1 = (tid + 256) >> 2,   ac1 = ((tid + 256) & 3) * 4;
    const int br[4] = { tid >> 6, (tid + 256) >> 6, (tid + 512) >> 6, (tid + 768) >> 6 };
    const int bc    = (tid & 63) * 4;

    const float* Ab = A + (size_t)m0 * K;
    const float* Bb = B + n0;

    float4 pa0 = *(const float4*)(Ab + (size_t)ar0 * K + ac0);
    float4 pa1 = *(const float4*)(Ab + (size_t)ar1 * K + ac1);
    float4 pb[4];
    #pragma unroll
    for (int t = 0; t < 4; t++)
        pb[t] = *(const float4*)(Bb + (size_t)br[t] * N + bc);

    float acc[4][8][4];
    #pragma unroll
    for (int mt = 0; mt < 4; mt++)
        #pragma unroll
        for (int nt = 0; nt < 8; nt++)
            #pragma unroll
            for (int r = 0; r < 4; r++) acc[mt][nt][r] = 0.f;

    for (int k0 = 0; k0 < K; k0 += BK) {
        As[(ac0 + 0) * AST + ar0] = f2tf(pa0.x);
        As[(ac0 + 1) * AST + ar0] = f2tf(pa0.y);
        As[(ac0 + 2) * AST + ar0] = f2tf(pa0.z);
        As[(ac0 + 3) * AST + ar0] = f2tf(pa0.w);
        As[(ac1 + 0) * AST + ar1] = f2tf(pa1.x);
        As[(ac1 + 1) * AST + ar1] = f2tf(pa1.y);
        As[(ac1 + 2) * AST + ar1] = f2tf(pa1.z);
        As[(ac1 + 3) * AST + ar1] = f2tf(pa1.w);
        #pragma unroll
        for (int t = 0; t < 4; t++) {
            uint4 u;
            u.x = f2tf(pb[t].x); u.y = f2tf(pb[t].y);
            u.z = f2tf(pb[t].z); u.w = f2tf(pb[t].w);
            *(uint4*)&Bs[br[t] * BST + bc] = u;
        }
        __syncthreads();

        if (k0 + BK < K) {
            pa0 = *(const float4*)(Ab + (size_t)ar0 * K + (k0 + BK) + ac0);
            pa1 = *(const float4*)(Ab + (size_t)ar1 * K + (k0 + BK) + ac1);
            #pragma unroll
            for (int t = 0; t < 4; t++)
                pb[t] = *(const float4*)(Bb + (size_t)(k0 + BK + br[t]) * N + bc);
        }

        #pragma unroll
        for (int ks = 0; ks < BK; ks += 8) {
            uint32_t af[4][4];
            #pragma unroll
            for (int mt = 0; mt < 4; mt++) {
                const int m = wm + mt * 16 + gr;
                const int ka = ks + gc;
                af[mt][0] = As[ka * AST + m];
                af[mt][1] = As[ka * AST + m + 8];
                af[mt][2] = As[(ka + 4) * AST + m];
                af[mt][3] = As[(ka + 4) * AST + m + 8];
            }
            #pragma unroll
            for (int nt = 0; nt < 8; nt++) {
                const int n = wn + nt * 8 + gr;
                const uint32_t b0 = Bs[(ks + gc) * BST + n];
                const uint32_t b1 = Bs[(ks + gc + 4) * BST + n];
                #pragma unroll
                for (int mt = 0; mt < 4; mt++)
                    mma_tf32(acc[mt][nt], af[mt][0], af[mt][1], af[mt][2], af[mt][3],
                             b0, b1);
            }
        }
        __syncthreads();
    }

    float2 bv[8];
    #pragma unroll
    for (int nt = 0; nt < 8; nt++)
        bv[nt] = *(const float2*)(bias + n0 + wn + nt * 8 + gc * 2);

    #pragma unroll
    for (int mt = 0; mt < 4; mt++) {
        const int gm = m0 + wm + mt * 16 + gr;
        #pragma unroll
        for (int nt = 0; nt < 8; nt++) {
            const int gn = n0 + wn + nt * 8 + gc * 2;
            float2 o0, o1;
            o0.x = acc[mt][nt][0] + bv[nt].x;
            o0.y = acc[mt][nt][1] + bv[nt].y;
            o1.x = acc[mt][nt][2] + bv[nt].x;
            o1.y = acc[mt][nt][3] + bv[nt].y;
            if (EPI == 1) {
                o0.x = fmaxf(o0.x, 0.f); o0.y = fmaxf(o0.y, 0.f);
                o1.x = fmaxf(o1.x, 0.f); o1.y = fmaxf(o1.y, 0.f);
            }
            if (EPI == 2) {
                const float2 r0 = *(const float2*)(R + (size_t)gm * N + gn);
                const float2 r1 = *(const float2*)(R + (size_t)(gm + 8) * N + gn);
                o0.x += r0.x; o0.y += r0.y;
                o1.x += r1.x; o1.y += r1.y;
            }
            *(float2*)(C + (size_t)gm * N + gn)       = o0;
            *(float2*)(C + (size_t)(gm + 8) * N + gn) = o1;
        }
    }
}

template<int EPI>
__global__ __launch_bounds__(256, 1) void tgemm_kernel(
    const float* __restrict__ A, const float* __restrict__ B,
    const float* __restrict__ bias, const float* __restrict__ R,
    float* __restrict__ C, int M, int N, int K)
{
    __shared__ uint32_t As[BK * AST];
    __shared__ uint32_t Bs[BK * BST];
    tgemm_body<EPI>(A, B, bias, R, C, M, N, K,
                    blockIdx.y * BM, blockIdx.x * BN, As, Bs);
}

__global__ __launch_bounds__(256, 1) void qkv_kernel(
    const float* __restrict__ A,
    const float* __restrict__ B0, const float* __restrict__ B1, const float* __restrict__ B2,
    const float* __restrict__ b0, const float* __restrict__ b1, const float* __restrict__ b2,
    float* __restrict__ C0, float* __restrict__ C1, float* __restrict__ C2)
{
    __shared__ uint32_t As[BK * AST];
    __shared__ uint32_t Bs[BK * BST];
    const float* B = (blockIdx.z == 0) ? B0 : (blockIdx.z == 1) ? B1 : B2;
    const float* bb = (blockIdx.z == 0) ? b0 : (blockIdx.z == 1) ? b1 : b2;
    float* C = (blockIdx.z == 0) ? C0 : (blockIdx.z == 1) ? C1 : C2;
    tgemm_body<0>(A, B, bb, nullptr, C, MTOT, EMB, EMB,
                  blockIdx.y * BM, blockIdx.x * BN, As, Bs);
}

// ---------------------------------------------------------------------------
// Flash-attention v3: tf32 tensor cores + log2-domain online softmax.
// grid = (SEQ/128, BATCH*HEADS), 256 threads (8 warps).
// Warp w owns q rows [w*16, w*16+16); full 64-key tile; full Dh=64.
// S phase:  S(16x64) = Q(16x64) @ K^T(64x64)   m16n8k8, 8 nt x 8 ksteps
// PV phase: O(16x64) += P(16x64) @ V(64x64)    m16n8k8, 8 nt x 8 ksteps
// P round-trips through per-warp smem (syncwarp only).
// smem (tf32 words): sQ[128][68] row-major, sK[64][72] d-major,
//                    sV[64][72] key-major, sP 8 x [16][68].
// ---------------------------------------------------------------------------
#define AQT 128
#define AKT 64
#define QP 68    // 68 mod 32 = 4  -> row-major fragment LDS conflict-free
#define KP 72    // 72 mod 32 = 8  -> d-major fragment LDS conflict-free
#define ATT_SMEM ((128*QP + 64*KP + 64*KP + 128*QP) * 4)   // 106496 B
#define QSCALE 0.18033688011112042f   // 0.125 * log2(e)

__global__ __launch_bounds__(256, 1) void attn3_kernel(
    const float* __restrict__ Q, const float* __restrict__ Km,
    const float* __restrict__ Vm, float* __restrict__ O)
{
    extern __shared__ uint32_t smu[];
    uint32_t* sQ = smu;                 // [128][QP]
    uint32_t* sK = sQ + 128 * QP;       // [64][KP]  (d-major: [d][key])
    uint32_t* sV = sK + 64 * KP;        // [64][KP]  (key-major: [key][d])
    uint32_t* sP = sV + 64 * KP;        // 8 x [16][QP]

    const int bh = blockIdx.y;
    const int b  = bh / HEADS;
    const int h  = bh % HEADS;
    const int q0 = blockIdx.x * AQT;
    const int tid  = threadIdx.x;
    const int warp = tid >> 5;
    const int lane = tid & 31;
    const int gr   = lane >> 2;   // 0..7
    const int gc   = lane & 3;    // 0..3
    const int wq0  = warp * 16;
    uint32_t* sPw = sP + warp * 16 * QP;

    const size_t base = ((size_t)b * SEQ) * EMB + (size_t)h * HDIM;
    const float* Qb = Q  + base;
    const float* Kb = Km + base;
    const float* Vb = Vm + base;

    // Q tile: 128 rows x 64 d, pre-scaled into log2 domain, tf32
    #pragma unroll
    for (int t = 0; t < 8; t++) {
        int idx = tid + t * 256;
        int qr = idx >> 4, c4 = (idx & 15) * 4;
        float4 v = *(const float4*)(Qb + (size_t)(q0 + qr) * EMB + c4);
        sQ[qr * QP + c4 + 0] = f2tf(v.x * QSCALE);
        sQ[qr * QP + c4 + 1] = f2tf(v.y * QSCALE);
        sQ[qr * QP + c4 + 2] = f2tf(v.z * QSCALE);
        sQ[qr * QP + c4 + 3] = f2tf(v.w * QSCALE);
    }

    float m0 = -1e30f, m1 = -1e30f, l0 = 0.f, l1 = 0.f;
    float oacc[8][4];
    #pragma unroll
    for (int nt = 0; nt < 8; nt++)
        #pragma unroll
        for (int r = 0; r < 4; r++) oacc[nt][r] = 0.f;

    // K/V prefetch (64 rows x 64 d each; 4 float4 per thread per matrix)
    const int kr0 = tid >> 4;
    const int kc4 = (tid & 15) * 4;
    float4 pk[4], pv[4];
    #pragma unroll
    for (int t = 0; t < 4; t++) {
        size_t goff = (size_t)(kr0 + t * 16) * EMB + kc4;
        pk[t] = *(const float4*)(Kb + goff);
        pv[t] = *(const float4*)(Vb + goff);
    }

    for (int kt = 0; kt < SEQ / AKT; kt++) {
        // commit K (d-major, tf32) and V (key-major, tf32)
        #pragma unroll
        for (int t = 0; t < 4; t++) {
            int kr = kr0 + t * 16;
            sK[(kc4 + 0) * KP + kr] = f2tf(pk[t].x);
            sK[(kc4 + 1) * KP + kr] = f2tf(pk[t].y);
            sK[(kc4 + 2) * KP + kr] = f2tf(pk[t].z);
            sK[(kc4 + 3) * KP + kr] = f2tf(pk[t].w);
            uint4 u;
            u.x = f2tf(pv[t].x); u.y = f2tf(pv[t].y);
            u.z = f2tf(pv[t].z); u.w = f2tf(pv[t].w);
            *(uint4*)&sV[kr * KP + kc4] = u;
        }
        __syncthreads();

        if (kt + 1 < SEQ / AKT) {
            const size_t tb = (size_t)(kt + 1) * AKT * EMB;
            #pragma unroll
            for (int t = 0; t < 4; t++) {
                size_t goff = tb + (size_t)(kr0 + t * 16) * EMB + kc4;
                pk[t] = *(const float4*)(Kb + goff);
                pv[t] = *(const float4*)(Vb + goff);
            }
        }

        // ---- S = Q @ K^T  (log2-scaled)
        float sacc[8][4];
        #pragma unroll
        for (int nt = 0; nt < 8; nt++)
            #pragma unroll
            for (int r = 0; r < 4; r++) sacc[nt][r] = 0.f;

        #pragma unroll
        for (int ks = 0; ks < 8; ks++) {
            const int ka = ks * 8 + gc;
            const uint32_t a0 = sQ[(wq0 + gr) * QP + ka];
            const uint32_t a1 = sQ[(wq0 + gr + 8) * QP + ka];
            const uint32_t a2 = sQ[(wq0 + gr) * QP + ka + 4];
            const uint32_t a3 = sQ[(wq0 + gr + 8) * QP + ka + 4];
            #pragma unroll
            for (int nt = 0; nt < 8; nt++) {
                const uint32_t b0 = sK[ka * KP + nt * 8 + gr];
                const uint32_t b1 = sK[(ka + 4) * KP + nt * 8 + gr];
                mma_tf32(sacc[nt], a0, a1, a2, a3, b0, b1);
            }
        }

        // ---- online softmax (base-2; rows gr and gr+8 of warp tile)
        float t0 = -1e30f, t1 = -1e30f;
        #pragma unroll
        for (int nt = 0; nt < 8; nt++) {
            t0 = fmaxf(t0, fmaxf(sacc[nt][0], sacc[nt][1]));
            t1 = fmaxf(t1, fmaxf(sacc[nt][2], sacc[nt][3]));
        }
        t0 = fmaxf(t0, __shfl_xor_sync(0xffffffffu, t0, 1));
        t0 = fmaxf(t0, __shfl_xor_sync(0xffffffffu, t0, 2));
        t1 = fmaxf(t1, __shfl_xor_sync(0xffffffffu, t1, 1));
        t1 = fmaxf(t1, __shfl_xor_sync(0xffffffffu, t1, 2));
        const float nm0 = fmaxf(m0, t0);
        const float nm1 = fmaxf(m1, t1);
        const float c0 = ex2(m0 - nm0);
        const float c1 = ex2(m1 - nm1);
        float ps0 = 0.f, ps1 = 0.f;
        #pragma unroll
        for (int nt = 0; nt < 8; nt++) {
            const float p00 = ex2(sacc[nt][0] - nm0);
            const float p01 = ex2(sacc[nt][1] - nm0);
            const float p10 = ex2(sacc[nt][2] - nm1);
            const float p11 = ex2(sacc[nt][3] - nm1);
            ps0 += p00 + p01;
            ps1 += p10 + p11;
            sPw[gr * QP + nt * 8 + gc * 2]           = f2tf(p00);
            sPw[gr * QP + nt * 8 + gc * 2 + 1]       = f2tf(p01);
            sPw[(gr + 8) * QP + nt * 8 + gc * 2]     = f2tf(p10);
            sPw[(gr + 8) * QP + nt * 8 + gc * 2 + 1] = f2tf(p11);
        }
        ps0 += __shfl_xor_sync(0xffffffffu, ps0, 1);
        ps0 += __shfl_xor_sync(0xffffffffu, ps0, 2);
        ps1 += __shfl_xor_sync(0xffffffffu, ps1, 1);
        ps1 += __shfl_xor_sync(0xffffffffu, ps1, 2);
        l0 = l0 * c0 + ps0;
        l1 = l1 * c1 + ps1;
        m0 = nm0; m1 = nm1;
        #pragma unroll
        for (int nt = 0; nt < 8; nt++) {
            oacc[nt][0] *= c0; oacc[nt][1] *= c0;
            oacc[nt][2] *= c1; oacc[nt][3] *= c1;
        }
        __syncwarp();

        // ---- O += P @ V
        #pragma unroll
        for (int ks = 0; ks < 8; ks++) {
            const int kk = ks * 8 + gc;
            const uint32_t a0 = sPw[gr * QP + kk];
            const uint32_t a1 = sPw[(gr + 8) * QP + kk];
            const uint32_t a2 = sPw[gr * QP + kk + 4];
            const uint32_t a3 = sPw[(gr + 8) * QP + kk + 4];
            #pragma unroll
            for (int nt = 0; nt < 8; nt++) {
                const uint32_t b0 = sV[kk * KP + nt * 8 + gr];
                const uint32_t b1 = sV[(kk + 4) * KP + nt * 8 + gr];
                mma_tf32(oacc[nt], a0, a1, a2, a3, b0, b1);
            }
        }
        __syncthreads();   // protect sK/sV before next commit
    }

    // epilogue
    const float inv0 = 1.0f / l0;
    const float inv1 = 1.0f / l1;
    float* O0 = O + base + (size_t)(q0 + wq0 + gr) * EMB;
    float* O1 = O + base + (size_t)(q0 + wq0 + gr + 8) * EMB;
    #pragma unroll
    for (int nt = 0; nt < 8; nt++) {
        const int cn = nt * 8 + gc * 2;
        float2 x0, x1;
        x0.x = oacc[nt][0] * inv0; x0.y = oacc[nt][1] * inv0;
        x1.x = oacc[nt][2] * inv1; x1.y = oacc[nt][3] * inv1;
        *(float2*)(O0 + cn) = x0;
        *(float2*)(O1 + cn) = x1;
    }
}

// ---------------------------------------------------------------------------
// Launch
// ---------------------------------------------------------------------------
extern "C" void kernel_launch(void* const* d_in, const int* in_sizes, int n_in,
                              void* d_out, int out_size)
{
    const float* x    = (const float*)d_in[0];
    const float* ln1g = (const float*)d_in[1];
    const float* ln1b = (const float*)d_in[2];
    const float* ln2g = (const float*)d_in[3];
    const float* ln2b = (const float*)d_in[4];
    const float* Wq   = (const float*)d_in[5];
    const float* bq   = (const float*)d_in[6];
    const float* Wk   = (const float*)d_in[7];
    const float* bk   = (const float*)d_in[8];
    const float* Wv   = (const float*)d_in[9];
    const float* bv   = (const float*)d_in[10];
    const float* Wo   = (const float*)d_in[11];
    const float* bo   = (const float*)d_in[12];
    const float* W1   = (const float*)d_in[13];
    const float* b1   = (const float*)d_in[14];
    const float* W2   = (const float*)d_in[15];
    const float* b2   = (const float*)d_in[16];
    float* out = (float*)d_out;

    float *xn, *q, *k, *v, *att, *x2, *xn2, *hb;
    cudaGetSymbolAddress((void**)&xn,  g_xn);
    cudaGetSymbolAddress((void**)&q,   g_q);
    cudaGetSymbolAddress((void**)&k,   g_k);
    cudaGetSymbolAddress((void**)&v,   g_v);
    cudaGetSymbolAddress((void**)&att, g_att);
    cudaGetSymbolAddress((void**)&x2,  g_x2);
    cudaGetSymbolAddress((void**)&xn2, g_xn2);
    cudaGetSymbolAddress((void**)&hb,  g_h);

    cudaFuncSetAttribute(attn3_kernel,
                         cudaFuncAttributeMaxDynamicSharedMemorySize, ATT_SMEM);

    const dim3 blk(256);
    const dim3 gQKV(EMB / BN, MTOT / BM, 3);
    const dim3 gEmb(EMB / BN, MTOT / BM);
    const dim3 gMlp(MLPH / BN, MTOT / BM);
    const dim3 gAtt(SEQ / AQT, BATCH * HEADS);

    // 1. LN1
    ln_kernel<<<MTOT, blk>>>(x, ln1g, ln1b, xn);
    // 2. QKV projections (fused launch, tf32 tensor cores)
    qkv_kernel<<<gQKV, blk>>>(xn, Wq, Wk, Wv, bq, bk, bv, q, k, v);
    // 3. Attention (tf32 tensor cores)
    attn3_kernel<<<gAtt, blk, ATT_SMEM>>>(q, k, v, att);
    // 4. Output projection + residual
    tgemm_kernel<2><<<gEmb, blk>>>(att, Wo, bo, x, x2, MTOT, EMB, EMB);
    // 5. LN2
    ln_kernel<<<MTOT, blk>>>(x2, ln2g, ln2b, xn2);
    // 6. MLP up + ReLU
    tgemm_kernel<1><<<gMlp, blk>>>(xn2, W1, b1, nullptr, hb, MTOT, MLPH, EMB);
    // 7. MLP down + residual -> output
    tgemm_kernel<2><<<gEmb, blk>>>(hb, W2, b2, x2, out, MTOT, EMB, MLPH);
}